// round 4
// baseline (speedup 1.0000x reference)
#include <cuda_runtime.h>

#define VOCAB   100000
#define DIMS    64
#define BATCH   16384
#define NNZ     50

// ---------------- packed f32x2 helpers (bitwise-identical fp32 lanes) ----------
__device__ __forceinline__ unsigned long long f2_add(unsigned long long a, unsigned long long b) {
    unsigned long long d;
    asm("add.rn.f32x2 %0, %1, %2;" : "=l"(d) : "l"(a), "l"(b));
    return d;
}
__device__ __forceinline__ unsigned long long f2_fma(unsigned long long a, unsigned long long b,
                                                     unsigned long long c) {
    unsigned long long d;
    asm("fma.rn.f32x2 %0, %1, %2, %3;" : "=l"(d) : "l"(a), "l"(b), "l"(c));
    return d;
}
__device__ __forceinline__ unsigned long long f2_dup(float x) {
    unsigned long long d;
    asm("mov.b64 %0, {%1, %1};" : "=l"(d) : "f"(x));
    return d;
}
__device__ __forceinline__ unsigned long long f2_pack(float lo, float hi) {
    unsigned long long d;
    asm("mov.b64 %0, {%1, %2};" : "=l"(d) : "f"(lo), "f"(hi));
    return d;
}
__device__ __forceinline__ void f2_unpack(unsigned long long v, float& lo, float& hi) {
    asm("mov.b64 {%0, %1}, %2;" : "=f"(lo), "=f"(hi) : "l"(v));
}

// ---------------- 4 MB scratch for the segment means ---------------------------
__device__ float g_xmean[BATCH * DIMS];

// ================================================================================
// Kernel 1: embedding gather + segment mean.
// No weights in SMEM -> high occupancy. 2-row groups, interleaved gathers.
// Lane l owns dims (2l, 2l+1) as one 8-byte load / packed add.
// ================================================================================
#define G1_BLOCKS  740                 // 5 blocks/SM * 148 SMs
#define G1_WARPS   (G1_BLOCKS * 8)     // 5920
#define G1_GROUPS  (BATCH / 2)         // 8192 two-row groups

__global__ void __launch_bounds__(256, 5)
gather_kernel(const float* __restrict__ emb, const int* __restrict__ fidx)
{
    __shared__ int sidx[8 * 104];      // per warp: 104 ints (100 used), 16B-aligned slices

    const int tid  = threadIdx.x;
    const int wid  = tid >> 5;
    const int lane = tid & 31;
    const int gw   = blockIdx.x * 8 + wid;

    const unsigned long long* __restrict__ embq = (const unsigned long long*)emb;
    int*        si  = sidx + wid * 104;
    const int2* si2 = (const int2*)si;

    for (int g = gw; g < G1_GROUPS; g += G1_WARPS) {
        const int row0 = g * 2;

        // stage 100 indices (both rows) via 25 coalesced int4 loads
        const int4* f4 = (const int4*)(fidx + g * 100);   // 400g bytes: 16B aligned
        if (lane < 25) ((int4*)si)[lane] = f4[lane];
        __syncwarp();

        unsigned long long acc0 = 0ull;   // bitpattern of {0.f, 0.f}
        unsigned long long acc1 = 0ull;

        // 25 int2 broadcast reads per row; 4 independent gathers per j-step.
        #pragma unroll 5
        for (int j = 0; j < 25; j++) {
            const int2 ia = si2[j];        // row0: k = 2j, 2j+1  (k-ascending order)
            const int2 ib = si2[25 + j];   // row1
            const unsigned long long e0 = __ldg(embq + (size_t)ia.x * 32 + lane);
            const unsigned long long e1 = __ldg(embq + (size_t)ia.y * 32 + lane);
            const unsigned long long e2 = __ldg(embq + (size_t)ib.x * 32 + lane);
            const unsigned long long e3 = __ldg(embq + (size_t)ib.y * 32 + lane);
            acc0 = f2_add(acc0, e0);
            acc0 = f2_add(acc0, e1);
            acc1 = f2_add(acc1, e2);
            acc1 = f2_add(acc1, e3);
        }
        __syncwarp();   // all lanes done with si before next group restages

        float a0x, a0y, a1x, a1y;
        f2_unpack(acc0, a0x, a0y);
        f2_unpack(acc1, a1x, a1y);
        const float inv = 1.f / NNZ;
        ((float2*)g_xmean)[(size_t)row0 * 32 + lane]       = make_float2(a0x * inv, a0y * inv);
        ((float2*)g_xmean)[(size_t)(row0 + 1) * 32 + lane] = make_float2(a1x * inv, a1y * inv);
    }
}

// ================================================================================
// Kernel 2: 3-layer MLP (64x64 each + bias + ReLU).
// 256 blocks x 128 threads; each warp owns 16 rows -> 1024 warps = 16384 rows.
// Weights in SMEM (per-lane float2 column reads, amortized over 16 rows).
// x broadcast: layer 0 from global scratch (L2-resident), layers 1-2 from SMEM.
// Packed f32x2 FMA halves fma-pipe issue count, bitwise-identical results.
// ================================================================================
#define G2_BLOCKS 256
// SMEM floats: weights 12288 | biases 192 | x staging 4 warps * 16 rows * 64
#define K2_OFF_B   12288
#define K2_OFF_X   12480
#define K2_SMEM_FLOATS (K2_OFF_X + 4 * 16 * 64)
#define K2_SMEM_BYTES  (K2_SMEM_FLOATS * 4)

__global__ void __launch_bounds__(128)
mlp_kernel(const float* __restrict__ W0, const float* __restrict__ b0,
           const float* __restrict__ W1, const float* __restrict__ b1,
           const float* __restrict__ W2, const float* __restrict__ b2,
           float* __restrict__ out)
{
    extern __shared__ float sm2[];
    float* Ws = sm2;
    float* bs = sm2 + K2_OFF_B;
    float* xs = sm2 + K2_OFF_X;

    const int tid  = threadIdx.x;
    const int wid  = tid >> 5;
    const int lane = tid & 31;

    // cooperative weight + bias load
    {
        const float* wsrc[3] = {W0, W1, W2};
        #pragma unroll
        for (int l = 0; l < 3; l++) {
            float4*       dst = (float4*)(Ws + l * 4096);
            const float4* src = (const float4*)wsrc[l];
            for (int i = tid; i < 1024; i += 128) dst[i] = src[i];
        }
        if (tid < 64) {
            bs[tid]       = b0[tid];
            bs[64  + tid] = b1[tid];
            bs[128 + tid] = b2[tid];
        }
    }
    __syncthreads();

    const int row0 = (blockIdx.x * 4 + wid) * 16;     // 16 rows per warp
    float* xw = xs + wid * (16 * 64);                  // per-warp staging

    unsigned long long y[16];

    #pragma unroll 1
    for (int layer = 0; layer < 3; layer++) {
        const float* wl = Ws + layer * 4096;
        const unsigned long long bv =
            f2_pack(bs[layer * 64 + 2 * lane], bs[layer * 64 + 2 * lane + 1]);

        #pragma unroll
        for (int r = 0; r < 16; r++) y[r] = bv;

        if (layer == 0) {
            #pragma unroll 4
            for (int dq = 0; dq < 16; dq++) {
                const unsigned long long w0 = *(const unsigned long long*)(wl + (dq * 4 + 0) * 64 + 2 * lane);
                const unsigned long long w1 = *(const unsigned long long*)(wl + (dq * 4 + 1) * 64 + 2 * lane);
                const unsigned long long w2 = *(const unsigned long long*)(wl + (dq * 4 + 2) * 64 + 2 * lane);
                const unsigned long long w3 = *(const unsigned long long*)(wl + (dq * 4 + 3) * 64 + 2 * lane);
                #pragma unroll
                for (int r = 0; r < 16; r++) {
                    const float4 xv = __ldg((const float4*)(g_xmean + (size_t)(row0 + r) * 64 + dq * 4));
                    y[r] = f2_fma(w0, f2_dup(xv.x), y[r]);
                    y[r] = f2_fma(w1, f2_dup(xv.y), y[r]);
                    y[r] = f2_fma(w2, f2_dup(xv.z), y[r]);
                    y[r] = f2_fma(w3, f2_dup(xv.w), y[r]);
                }
            }
        } else {
            #pragma unroll 4
            for (int dq = 0; dq < 16; dq++) {
                const unsigned long long w0 = *(const unsigned long long*)(wl + (dq * 4 + 0) * 64 + 2 * lane);
                const unsigned long long w1 = *(const unsigned long long*)(wl + (dq * 4 + 1) * 64 + 2 * lane);
                const unsigned long long w2 = *(const unsigned long long*)(wl + (dq * 4 + 2) * 64 + 2 * lane);
                const unsigned long long w3 = *(const unsigned long long*)(wl + (dq * 4 + 3) * 64 + 2 * lane);
                #pragma unroll
                for (int r = 0; r < 16; r++) {
                    const float4 xv = *(const float4*)(xw + r * 64 + dq * 4);   // broadcast LDS
                    y[r] = f2_fma(w0, f2_dup(xv.x), y[r]);
                    y[r] = f2_fma(w1, f2_dup(xv.y), y[r]);
                    y[r] = f2_fma(w2, f2_dup(xv.z), y[r]);
                    y[r] = f2_fma(w3, f2_dup(xv.w), y[r]);
                }
            }
        }

        // ReLU
        #pragma unroll
        for (int r = 0; r < 16; r++) {
            float lo, hi;
            f2_unpack(y[r], lo, hi);
            y[r] = f2_pack(fmaxf(lo, 0.f), fmaxf(hi, 0.f));
        }

        if (layer < 2) {
            __syncwarp();   // lanes finished reading xw
            #pragma unroll
            for (int r = 0; r < 16; r++)
                *(unsigned long long*)(xw + r * 64 + 2 * lane) = y[r];
            __syncwarp();   // stores visible before next layer's reads
        } else {
            #pragma unroll
            for (int r = 0; r < 16; r++)
                *(unsigned long long*)(out + (size_t)(row0 + r) * 64 + 2 * lane) = y[r];
        }
    }
}

// ================================================================================
extern "C" void kernel_launch(void* const* d_in, const int* in_sizes, int n_in,
                              void* d_out, int out_size)
{
    // Resolve inputs by element count:
    //   6,400,000 -> emb_table ; 819,200 (first) -> feature_indices
    //   (second 819,200 = batch_indices, implied by structure) ;
    //   4096 -> W0,W1,W2 in order ; 64 -> b0,b1,b2 in order.
    const float* emb = nullptr;
    const int*   fi  = nullptr;
    const float* W[3] = {nullptr, nullptr, nullptr};
    const float* b[3] = {nullptr, nullptr, nullptr};
    int nw = 0, nb = 0, nidx = 0;

    for (int i = 0; i < n_in; i++) {
        const int s = in_sizes[i];
        if (s == VOCAB * DIMS) {
            emb = (const float*)d_in[i];
        } else if (s == BATCH * NNZ) {
            if (nidx++ == 0) fi = (const int*)d_in[i];
        } else if (s == DIMS * DIMS) {
            if (nw < 3) W[nw++] = (const float*)d_in[i];
        } else if (s == DIMS) {
            if (nb < 3) b[nb++] = (const float*)d_in[i];
        }
    }

    cudaFuncSetAttribute(mlp_kernel,
                         cudaFuncAttributeMaxDynamicSharedMemorySize, K2_SMEM_BYTES);

    gather_kernel<<<G1_BLOCKS, 256>>>(emb, fi);
    mlp_kernel<<<G2_BLOCKS, 128, K2_SMEM_BYTES>>>(W[0], b[0], W[1], b[1], W[2], b[2],
                                                  (float*)d_out);
}